// round 3
// baseline (speedup 1.0000x reference)
#include <cuda_runtime.h>
#include <cuda_bf16.h>
#include <stdint.h>

// ApplyRotary: T=32768 tokens, H=32 heads, D=128, ROPE_DIM=64.
// out[t,h,d<32]    =  x[d]*cos[d] - x[d+32]*sin[d]
// out[t,h,32<=d<64]=  x[d]*cos[d] + x[d-32]*sin[d]
// out[t,h,d>=64]   =  x[d]
//
// One WARP per TOKEN per grid-stride iteration. Persistent grid of exactly
// 148 SMs x 5 resident blocks = 740 blocks (no wave quantization).
// Streaming cache hints: __ldcs for input (never re-read), __stcs for
// output (never read back); __ldg for the reused sin/cos/cu tables.

#define N_TOK   32768
#define N_HEAD  32
#define ROPE    64
#define GRID    740        // 148 SMs * 5 resident blocks
#define WPB     8          // warps per block

__global__ __launch_bounds__(256, 5) void rope_kernel(
    const float* __restrict__ in,
    const float* __restrict__ sin_c,
    const float* __restrict__ cos_c,
    const int*   __restrict__ cu,
    float*       __restrict__ out)
{
    const int warp = threadIdx.x >> 5;
    const int lane = threadIdx.x & 31;
    const float sg = (lane < 8) ? -1.0f : 1.0f;

    for (int t = blockIdx.x * WPB + warp; t < N_TOK; t += GRID * WPB) {
        // Branchless binary search: largest idx in [0,16] with cu[idx] <= t.
        int lo = 0;
#pragma unroll
        for (int half = 16; half > 0; half >>= 1) {
            int mid = lo + half;
            if (mid <= 16 && __ldg(cu + mid) <= t) lo = mid;
        }
        const int off = t - __ldg(cu + lo);

        // sin/cos for this token, held in registers for all 32 heads.
        float4 s4 = make_float4(0.f, 0.f, 0.f, 0.f);
        float4 c4 = s4;
        if (lane < 16) {
            s4 = __ldg(reinterpret_cast<const float4*>(sin_c + (size_t)off * ROPE) + lane);
            c4 = __ldg(reinterpret_cast<const float4*>(cos_c + (size_t)off * ROPE) + lane);
        }

        const float4* in4  = reinterpret_cast<const float4*>(in) + (size_t)t * (N_HEAD * 32) + lane;
        float4*       out4 = reinterpret_cast<float4*>(out)      + (size_t)t * (N_HEAD * 32) + lane;

#pragma unroll 2
        for (int h0 = 0; h0 < N_HEAD; h0 += 4) {
            float4 v[4];
#pragma unroll
            for (int i = 0; i < 4; i++)
                v[i] = __ldcs(in4 + (size_t)(h0 + i) * 32);

#pragma unroll
            for (int i = 0; i < 4; i++) {
                float4 q;
                q.x = __shfl_xor_sync(0xffffffffu, v[i].x, 8);
                q.y = __shfl_xor_sync(0xffffffffu, v[i].y, 8);
                q.z = __shfl_xor_sync(0xffffffffu, v[i].z, 8);
                q.w = __shfl_xor_sync(0xffffffffu, v[i].w, 8);

                float4 r = v[i];
                if (lane < 16) {
                    r.x = fmaf(sg * q.x, s4.x, v[i].x * c4.x);
                    r.y = fmaf(sg * q.y, s4.y, v[i].y * c4.y);
                    r.z = fmaf(sg * q.z, s4.z, v[i].z * c4.z);
                    r.w = fmaf(sg * q.w, s4.w, v[i].w * c4.w);
                }
                __stcs(out4 + (size_t)(h0 + i) * 32, r);
            }
        }
    }
}

extern "C" void kernel_launch(void* const* d_in, const int* in_sizes, int n_in,
                              void* d_out, int out_size)
{
    const float* in    = (const float*)d_in[0];
    const float* sin_c = (const float*)d_in[1];
    const float* cos_c = (const float*)d_in[2];
    const int*   cu    = (const int*)  d_in[3];
    float*       out   = (float*)d_out;

    rope_kernel<<<GRID, 256>>>(in, sin_c, cos_c, cu, out);
}

// round 4
// speedup vs baseline: 1.0913x; 1.0913x over previous
#include <cuda_runtime.h>
#include <cuda_bf16.h>
#include <stdint.h>

// ApplyRotary: T=32768 tokens, H=32 heads, D=128, ROPE_DIM=64.
// out[t,h,d<32]    =  x[d]*cos[d] - x[d+32]*sin[d]
// out[t,h,32<=d<64]=  x[d]*cos[d] + x[d-32]*sin[d]
// out[t,h,d>=64]   =  x[d]
//
// One WARP per TOKEN (grid = T/8 blocks of 8 warps; R2 structure — the
// persistent variant regressed by re-paying the search chain mid-stream).
// Software-pipelined: chunk c+1's 4x LDG.128 issue before chunk c's
// FMA+STG, so reads stay in flight during the write phase.

#define N_TOK   32768
#define N_HEAD  32
#define ROPE    64

__global__ __launch_bounds__(256, 4) void rope_kernel(
    const float* __restrict__ in,
    const float* __restrict__ sin_c,
    const float* __restrict__ cos_c,
    const int*   __restrict__ cu,
    float*       __restrict__ out)
{
    const int warp = threadIdx.x >> 5;
    const int lane = threadIdx.x & 31;
    const int t    = blockIdx.x * 8 + warp;   // one token per warp

    // Branchless binary search: largest idx in [0,16] with cu[idx] <= t.
    int lo = 0;
#pragma unroll
    for (int half = 16; half > 0; half >>= 1) {
        int mid = lo + half;
        if (mid <= 16 && __ldg(cu + mid) <= t) lo = mid;
    }
    const int off = t - __ldg(cu + lo);

    // sin/cos for this token, held in registers for all 32 heads.
    float4 s4 = make_float4(0.f, 0.f, 0.f, 0.f);
    float4 c4 = s4;
    if (lane < 16) {
        s4 = __ldg(reinterpret_cast<const float4*>(sin_c + (size_t)off * ROPE) + lane);
        c4 = __ldg(reinterpret_cast<const float4*>(cos_c + (size_t)off * ROPE) + lane);
    }
    const float sg = (lane < 8) ? -1.0f : 1.0f;

    const float4* in4  = reinterpret_cast<const float4*>(in) + (size_t)t * (N_HEAD * 32) + lane;
    float4*       out4 = reinterpret_cast<float4*>(out)      + (size_t)t * (N_HEAD * 32) + lane;

    // 8 chunks of 4 heads. Double-buffered, fully unrolled (buffers rename).
    float4 v[4], w[4];
#pragma unroll
    for (int i = 0; i < 4; i++)
        v[i] = __ldg(in4 + (size_t)i * 32);

#pragma unroll
    for (int c = 0; c < 8; c++) {
        const int h0 = c * 4;
        if (c < 7) {
#pragma unroll
            for (int i = 0; i < 4; i++)
                w[i] = __ldg(in4 + (size_t)(h0 + 4 + i) * 32);
        }

#pragma unroll
        for (int i = 0; i < 4; i++) {
            float4 q;
            q.x = __shfl_xor_sync(0xffffffffu, v[i].x, 8);
            q.y = __shfl_xor_sync(0xffffffffu, v[i].y, 8);
            q.z = __shfl_xor_sync(0xffffffffu, v[i].z, 8);
            q.w = __shfl_xor_sync(0xffffffffu, v[i].w, 8);

            float4 r = v[i];
            if (lane < 16) {
                r.x = fmaf(sg * q.x, s4.x, v[i].x * c4.x);
                r.y = fmaf(sg * q.y, s4.y, v[i].y * c4.y);
                r.z = fmaf(sg * q.z, s4.z, v[i].z * c4.z);
                r.w = fmaf(sg * q.w, s4.w, v[i].w * c4.w);
            }
            out4[(size_t)(h0 + i) * 32] = r;
        }

#pragma unroll
        for (int i = 0; i < 4; i++)
            v[i] = w[i];
    }
}

extern "C" void kernel_launch(void* const* d_in, const int* in_sizes, int n_in,
                              void* d_out, int out_size)
{
    const float* in    = (const float*)d_in[0];
    const float* sin_c = (const float*)d_in[1];
    const float* cos_c = (const float*)d_in[2];
    const int*   cu    = (const int*)  d_in[3];
    float*       out   = (float*)d_out;

    const int blocks = N_TOK / 8;   // 4096 blocks, 8 warps each
    rope_kernel<<<blocks, 256>>>(in, sin_c, cos_c, cu, out);
}

// round 5
// speedup vs baseline: 1.0941x; 1.0026x over previous
#include <cuda_runtime.h>
#include <cuda_bf16.h>
#include <stdint.h>

// ApplyRotary: T=32768 tokens, H=32 heads, D=128, ROPE_DIM=64.
// out[t,h,d<32]    =  x[d]*cos[d] - x[d+32]*sin[d]
// out[t,h,32<=d<64]=  x[d]*cos[d] + x[d-32]*sin[d]
// out[t,h,d>=64]   =  x[d]
//
// One WARP per TOKEN. 256-bit global ld/st (sm_100+): each lane moves
// 32 B, a warp-instruction covers 2 heads (1 KB). Each head spans 16
// lanes; rope partner (d +/- 32) is 4 lanes away -> shfl.xor(4).
// Chunks of 4 heads (2x LDG.256), double-buffered as in R3.

#define N_TOK   32768
#define N_HEAD  32
#define ROPE    64

__device__ __forceinline__ void ldg256(const float* p, float r[8]) {
    asm volatile("ld.global.nc.v8.f32 {%0,%1,%2,%3,%4,%5,%6,%7}, [%8];"
        : "=f"(r[0]), "=f"(r[1]), "=f"(r[2]), "=f"(r[3]),
          "=f"(r[4]), "=f"(r[5]), "=f"(r[6]), "=f"(r[7])
        : "l"(p));
}

__device__ __forceinline__ void stg256(float* p, const float r[8]) {
    asm volatile("st.global.v8.f32 [%0], {%1,%2,%3,%4,%5,%6,%7,%8};"
        :: "l"(p),
           "f"(r[0]), "f"(r[1]), "f"(r[2]), "f"(r[3]),
           "f"(r[4]), "f"(r[5]), "f"(r[6]), "f"(r[7])
        : "memory");
}

__global__ __launch_bounds__(256, 3) void rope_kernel(
    const float* __restrict__ in,
    const float* __restrict__ sin_c,
    const float* __restrict__ cos_c,
    const int*   __restrict__ cu,
    float*       __restrict__ out)
{
    const int warp = threadIdx.x >> 5;
    const int lane = threadIdx.x & 31;
    const int t    = blockIdx.x * 8 + warp;   // one token per warp

    // il = lane within the 16-lane head span; this lane owns floats
    // d = [8*il, 8*il+8) of its head.
    const int il = lane & 15;

    // Branchless binary search: largest idx in [0,16] with cu[idx] <= t.
    int lo = 0;
#pragma unroll
    for (int half = 16; half > 0; half >>= 1) {
        int mid = lo + half;
        if (mid <= 16 && __ldg(cu + mid) <= t) lo = mid;
    }
    const int off = t - __ldg(cu + lo);

    // sin/cos for this lane's 8 rope dims (only il<8 touches rope region).
    float s8[8], c8[8];
#pragma unroll
    for (int k = 0; k < 8; k++) { s8[k] = 0.f; c8[k] = 0.f; }
    if (il < 8) {
        ldg256(sin_c + (size_t)off * ROPE + 8 * il, s8);
        ldg256(cos_c + (size_t)off * ROPE + 8 * il, c8);
    }
    const float sg   = (il < 4) ? -1.0f : 1.0f;
    const bool  rope = (il < 8);

    const float* inb  = in  + (size_t)t * (N_HEAD * 128) + 8 * lane;
    float*       outb = out + (size_t)t * (N_HEAD * 128) + 8 * lane;

    // 8 chunks of 4 heads (= 2 x 1KB blocks). Double-buffered.
    float v[2][8], w[2][8];
#pragma unroll
    for (int j = 0; j < 2; j++)
        ldg256(inb + 256 * j, v[j]);

#pragma unroll
    for (int c = 0; c < 8; c++) {
        if (c < 7) {
#pragma unroll
            for (int j = 0; j < 2; j++)
                ldg256(inb + 512 * (c + 1) + 256 * j, w[j]);
        }

#pragma unroll
        for (int j = 0; j < 2; j++) {
            float r[8];
#pragma unroll
            for (int k = 0; k < 8; k++) {
                const float q = __shfl_xor_sync(0xffffffffu, v[j][k], 4);
                r[k] = rope ? fmaf(sg * q, s8[k], v[j][k] * c8[k]) : v[j][k];
            }
            stg256(outb + 512 * c + 256 * j, r);
        }

#pragma unroll
        for (int j = 0; j < 2; j++)
#pragma unroll
            for (int k = 0; k < 8; k++)
                v[j][k] = w[j][k];
    }
}

extern "C" void kernel_launch(void* const* d_in, const int* in_sizes, int n_in,
                              void* d_out, int out_size)
{
    const float* in    = (const float*)d_in[0];
    const float* sin_c = (const float*)d_in[1];
    const float* cos_c = (const float*)d_in[2];
    const int*   cu    = (const int*)  d_in[3];
    float*       out   = (float*)d_out;

    const int blocks = N_TOK / 8;   // 4096 blocks, 8 warps each
    rope_kernel<<<blocks, 256>>>(in, sin_c, cos_c, cu, out);
}